// round 1
// baseline (speedup 1.0000x reference)
#include <cuda_runtime.h>
#include <math.h>

#define BATCH  2
#define SEQ    2048
#define DMODEL 1024
#define DINNER 1024
#define DSTATE 16
#define DTRANK 64
#define DCONV  4
#define ML     (BATCH * SEQ)            /* 4096 rows */
#define XDBLW  (DTRANK + 2 * DSTATE)    /* 96 */

// ---------------- scratch (no allocs allowed) ----------------
__device__ float g_xz[(size_t)ML * 2 * DINNER];   // in_proj output [4096, 2048]
__device__ float g_xconv[(size_t)ML * DINNER];    // conv+SiLU output
__device__ float g_xdbl[(size_t)ML * XDBLW];      // [dt_raw | B | C]
__device__ float g_dt[(size_t)ML * DINNER];       // softplus(dt)
__device__ float g_yscan[(size_t)ML * DINNER];    // scan output
__device__ float g_ygate[(size_t)ML * DINNER];    // gated output

__device__ __forceinline__ float sigmoid_f(float x) {
    return 1.0f / (1.0f + __expf(-x));
}

// ---------------- 128x128x8 fp32 GEMM: C[M,N] = A[M,K] @ B[N,K]^T ----------------
// Requires: M,N multiples of 128, K multiple of 8, 16B-aligned rows.
// ACT==1: C = softplus(C + bias[col])
template <int ACT>
__global__ __launch_bounds__(256) void gemm128(
    const float* __restrict__ A, int lda,
    const float* __restrict__ B, int ldb,
    float* __restrict__ C, int ldc, int K,
    const float* __restrict__ bias)
{
    __shared__ float As[8][128];
    __shared__ float Bs[8][128];

    const int tid  = threadIdx.x;
    const int bm   = blockIdx.y * 128;
    const int bn   = blockIdx.x * 128;
    const int arow = tid >> 1;          // 0..127
    const int acol = (tid & 1) * 4;     // 0 or 4
    const int tx   = tid & 15;
    const int ty   = tid >> 4;

    const float* Ap = A + (size_t)(bm + arow) * lda + acol;
    const float* Bp = B + (size_t)(bn + arow) * ldb + acol;

    float acc[8][8];
#pragma unroll
    for (int i = 0; i < 8; i++)
#pragma unroll
        for (int j = 0; j < 8; j++) acc[i][j] = 0.0f;

    for (int k0 = 0; k0 < K; k0 += 8) {
        float4 a = *(const float4*)(Ap + k0);
        float4 b = *(const float4*)(Bp + k0);
        As[acol + 0][arow] = a.x; As[acol + 1][arow] = a.y;
        As[acol + 2][arow] = a.z; As[acol + 3][arow] = a.w;
        Bs[acol + 0][arow] = b.x; Bs[acol + 1][arow] = b.y;
        Bs[acol + 2][arow] = b.z; Bs[acol + 3][arow] = b.w;
        __syncthreads();
#pragma unroll
        for (int k = 0; k < 8; k++) {
            float4 a0 = *(const float4*)&As[k][ty * 8];
            float4 a1 = *(const float4*)&As[k][ty * 8 + 4];
            float4 b0 = *(const float4*)&Bs[k][tx * 8];
            float4 b1 = *(const float4*)&Bs[k][tx * 8 + 4];
            float ra[8] = {a0.x, a0.y, a0.z, a0.w, a1.x, a1.y, a1.z, a1.w};
            float rb[8] = {b0.x, b0.y, b0.z, b0.w, b1.x, b1.y, b1.z, b1.w};
#pragma unroll
            for (int i = 0; i < 8; i++)
#pragma unroll
                for (int j = 0; j < 8; j++)
                    acc[i][j] += ra[i] * rb[j];
        }
        __syncthreads();
    }

#pragma unroll
    for (int i = 0; i < 8; i++) {
        const int row = bm + ty * 8 + i;
#pragma unroll
        for (int j = 0; j < 8; j++) {
            const int col = bn + tx * 8 + j;
            float v = acc[i][j];
            if (ACT == 1) {
                v += bias[col];
                v = (v > 20.0f) ? v : log1pf(__expf(v));  // softplus
            }
            C[(size_t)row * ldc + col] = v;
        }
    }
}

// ---------------- small GEMM for x_dbl: [ML,1024] @ [96,1024]^T -> [ML,96] ----------------
__global__ __launch_bounds__(256) void gemm_xdbl(
    const float* __restrict__ A,   // g_xconv [ML, DINNER]
    const float* __restrict__ W,   // W_x [96, DINNER]
    float* __restrict__ C)         // [ML, 96]
{
    __shared__ float As[16][32];
    __shared__ float Ws[16][96];
    const int tid = threadIdx.x;
    const int bm  = blockIdx.x * 32;
    const int tx  = tid & 15;   // col group: cols tx + 16*j, j<6
    const int ty  = tid >> 4;   // row group: rows ty, ty+16

    float acc[2][6];
#pragma unroll
    for (int i = 0; i < 2; i++)
#pragma unroll
        for (int j = 0; j < 6; j++) acc[i][j] = 0.0f;

    for (int k0 = 0; k0 < DINNER; k0 += 16) {
        for (int e = tid; e < 32 * 16; e += 256) {
            int r = e >> 4, kk = e & 15;
            As[kk][r] = A[(size_t)(bm + r) * DINNER + k0 + kk];
        }
        for (int e = tid; e < 96 * 16; e += 256) {
            int n = e >> 4, kk = e & 15;
            Ws[kk][n] = W[(size_t)n * DINNER + k0 + kk];
        }
        __syncthreads();
#pragma unroll
        for (int k = 0; k < 16; k++) {
            float ra0 = As[k][ty];
            float ra1 = As[k][ty + 16];
#pragma unroll
            for (int j = 0; j < 6; j++) {
                float wb = Ws[k][tx + 16 * j];
                acc[0][j] += ra0 * wb;
                acc[1][j] += ra1 * wb;
            }
        }
        __syncthreads();
    }
#pragma unroll
    for (int i = 0; i < 2; i++)
#pragma unroll
        for (int j = 0; j < 6; j++)
            C[(size_t)(bm + ty + 16 * i) * XDBLW + tx + 16 * j] = acc[i][j];
}

// ---------------- causal depthwise conv (k=4) + SiLU ----------------
__global__ void conv_silu_kernel(
    const float* __restrict__ xz,       // [ML, 2*DINNER], x_ssm = cols [0,1024)
    const float* __restrict__ w,        // [DINNER, 1, 4]
    const float* __restrict__ cb,       // [DINNER]
    float* __restrict__ out)            // [ML, DINNER]
{
    int idx = blockIdx.x * blockDim.x + threadIdx.x;
    if (idx >= ML * DINNER) return;
    int d  = idx & (DINNER - 1);
    int bl = idx >> 10;
    int l  = bl & (SEQ - 1);

    float w0 = w[d * 4 + 0], w1 = w[d * 4 + 1], w2 = w[d * 4 + 2], w3 = w[d * 4 + 3];
    const float* base = xz + (size_t)bl * (2 * DINNER) + d;
    float acc = cb[d] + base[0] * w3;                       // tap j=3 -> x[l]
    if (l >= 1) acc += base[-(2 * DINNER)]     * w2;
    if (l >= 2) acc += base[-2 * (2 * DINNER)] * w1;
    if (l >= 3) acc += base[-3 * (2 * DINNER)] * w0;
    out[idx] = acc * sigmoid_f(acc);
}

// ---------------- selective scan: 16 lanes per (b,d) channel ----------------
__global__ void scan_kernel(
    const float* __restrict__ dt,     // [ML, DINNER]
    const float* __restrict__ xc,     // [ML, DINNER]
    const float* __restrict__ xdbl,   // [ML, 96]  (B at 64, C at 80)
    const float* __restrict__ A_log,  // [DINNER, DSTATE]
    float* __restrict__ y)            // [ML, DINNER]
{
    int gtid = blockIdx.x * blockDim.x + threadIdx.x;
    int ch = gtid >> 4;                  // channel 0..2047
    int n  = gtid & 15;                  // state index
    if (ch >= BATCH * DINNER) return;
    int b = ch / DINNER;
    int d = ch - b * DINNER;

    const float Aval = -__expf(A_log[d * DSTATE + n]);
    float h = 0.0f;

    const float* bp = xdbl + (size_t)b * SEQ * XDBLW + DTRANK + n;
    const float* cp = bp + DSTATE;
    size_t base = (size_t)b * SEQ * DINNER + d;

    for (int l = 0; l < SEQ; l++) {
        float dtv = dt[base];            // broadcast across 16 lanes
        float xv  = xc[base];
        float Bv  = bp[0];
        float Cv  = cp[0];
        h = __expf(dtv * Aval) * h + (dtv * xv) * Bv;
        float yv = h * Cv;
        yv += __shfl_down_sync(0xffffffffu, yv, 8, 16);
        yv += __shfl_down_sync(0xffffffffu, yv, 4, 16);
        yv += __shfl_down_sync(0xffffffffu, yv, 2, 16);
        yv += __shfl_down_sync(0xffffffffu, yv, 1, 16);
        if (n == 0) y[base] = yv;
        base += DINNER;
        bp += XDBLW;
        cp += XDBLW;
    }
}

// ---------------- y = (y_scan + x_conv*D) * silu(z) ----------------
__global__ void gate_kernel(
    const float* __restrict__ ys,
    const float* __restrict__ xc,
    const float* __restrict__ xz,      // z = cols [1024,2048)
    const float* __restrict__ Dp,
    float* __restrict__ out)
{
    int idx = blockIdx.x * blockDim.x + threadIdx.x;
    if (idx >= ML * DINNER) return;
    int d  = idx & (DINNER - 1);
    int bl = idx >> 10;
    float z = xz[(size_t)bl * (2 * DINNER) + DINNER + d];
    out[idx] = (ys[idx] + xc[idx] * Dp[d]) * (z * sigmoid_f(z));
}

// ---------------- launch ----------------
extern "C" void kernel_launch(void* const* d_in, const int* in_sizes, int n_in,
                              void* d_out, int out_size)
{
    const float* x      = (const float*)d_in[0];
    const float* W_in   = (const float*)d_in[1];
    const float* conv_w = (const float*)d_in[2];
    const float* conv_b = (const float*)d_in[3];
    const float* W_x    = (const float*)d_in[4];
    const float* W_dt   = (const float*)d_in[5];
    const float* b_dt   = (const float*)d_in[6];
    const float* A_log  = (const float*)d_in[7];
    const float* Dp     = (const float*)d_in[8];
    const float* W_out  = (const float*)d_in[9];
    float* out = (float*)d_out;

    float *xz, *xconv, *xdbl, *dt, *yscan, *ygate;
    cudaGetSymbolAddress((void**)&xz,    g_xz);
    cudaGetSymbolAddress((void**)&xconv, g_xconv);
    cudaGetSymbolAddress((void**)&xdbl,  g_xdbl);
    cudaGetSymbolAddress((void**)&dt,    g_dt);
    cudaGetSymbolAddress((void**)&yscan, g_yscan);
    cudaGetSymbolAddress((void**)&ygate, g_ygate);

    // 1) xz = x @ W_in^T      [4096,2048]
    gemm128<0><<<dim3(2 * DINNER / 128, ML / 128), 256>>>(
        x, DMODEL, W_in, DMODEL, xz, 2 * DINNER, DMODEL, nullptr);

    // 2) causal conv + SiLU   [4096,1024]
    conv_silu_kernel<<<(ML * DINNER) / 256, 256>>>(xz, conv_w, conv_b, xconv);

    // 3) x_dbl = x_conv @ W_x^T  [4096,96]
    gemm_xdbl<<<ML / 32, 256>>>(xconv, W_x, xdbl);

    // 4) dt = softplus(dt_raw @ W_dt^T + b_dt)  [4096,1024]
    gemm128<1><<<dim3(DINNER / 128, ML / 128), 256>>>(
        xdbl, XDBLW, W_dt, DTRANK, dt, DINNER, DTRANK, b_dt);

    // 5) selective scan  [4096,1024]
    scan_kernel<<<(BATCH * DINNER * DSTATE) / 256, 256>>>(dt, xconv, xdbl, A_log, yscan);

    // 6) gating
    gate_kernel<<<(ML * DINNER) / 256, 256>>>(yscan, xconv, xz, Dp, ygate);

    // 7) out = y @ W_out^T  [4096,1024]
    gemm128<0><<<dim3(DMODEL / 128, ML / 128), 256>>>(
        ygate, DINNER, W_out, DINNER, out, DMODEL, DINNER, nullptr);
}

// round 2
// speedup vs baseline: 1.8193x; 1.8193x over previous
#include <cuda_runtime.h>
#include <math.h>
#include <stdint.h>

#define BATCH  2
#define SEQ    2048
#define DMODEL 1024
#define DINNER 1024
#define DSTATE 16
#define DTRANK 64
#define ML     (BATCH * SEQ)            /* 4096 rows */
#define XDBLW  (DTRANK + 2 * DSTATE)    /* 96 */

// ---------------- scratch (no allocs allowed) ----------------
__device__ float g_xz[(size_t)ML * 2 * DINNER];   // in_proj output [4096, 2048]
__device__ float g_xconv[(size_t)ML * DINNER];    // conv+SiLU output
__device__ float g_xdbl[(size_t)ML * XDBLW];      // [dt_raw | B | C]
__device__ float g_dt[(size_t)ML * DINNER];       // softplus(dt)
__device__ float g_yscan[(size_t)ML * DINNER];    // scan output
__device__ float g_ygate[(size_t)ML * DINNER];    // gated output

__device__ __forceinline__ float sigmoid_f(float x) {
    return 1.0f / (1.0f + __expf(-x));
}

__device__ __forceinline__ uint32_t f2tf32(float x) {
    uint32_t r;
    asm("cvt.rna.tf32.f32 %0, %1;" : "=r"(r) : "f"(x));
    return r;
}

__device__ __forceinline__ void mma_tf32(float* d, const uint32_t* a, const uint32_t* b) {
    asm volatile(
        "mma.sync.aligned.m16n8k8.row.col.f32.tf32.tf32.f32 "
        "{%0,%1,%2,%3}, {%4,%5,%6,%7}, {%8,%9}, {%0,%1,%2,%3};"
        : "+f"(d[0]), "+f"(d[1]), "+f"(d[2]), "+f"(d[3])
        : "r"(a[0]), "r"(a[1]), "r"(a[2]), "r"(a[3]), "r"(b[0]), "r"(b[1]));
}

// ---------------- TF32 tensor-core GEMM: C[M,N] = A[M,K] @ B[N,K]^T ----------------
// Tiles: 128x128x16, 256 threads (8 warps, 2x4), warp tile 64x32.
// M multiple of 128, K multiple of 16, grid covers N rounded up to 128;
// Nvalid guards B loads + C stores (for N=96 case).
// ACT==1: C = softplus(C + bias[col])
template <int ACT>
__global__ __launch_bounds__(256, 2) void gemm_tf32(
    const float* __restrict__ A, int lda,
    const float* __restrict__ B, int ldb,
    float* __restrict__ C, int ldc,
    int K, int Nvalid,
    const float* __restrict__ bias)
{
    __shared__ uint32_t As[128][20];   // [m][k], pad->stride 20 (conflict-free frags)
    __shared__ uint32_t Bs[128][20];   // [n][k]

    const int tid  = threadIdx.x;
    const int bm   = blockIdx.y * 128;
    const int bn   = blockIdx.x * 128;

    // gmem tile fill mapping: each thread loads 2 float4 per operand
    const int lrow = tid >> 1;            // 0..127
    const int lcol = (tid & 1) * 8;       // 0 or 8

    const int warp = tid >> 5;
    const int lane = tid & 31;
    const int wm   = (warp >> 2) * 64;    // warp row offset (0/64)
    const int wn   = (warp & 3) * 32;     // warp col offset
    const int gid  = lane >> 2;           // 0..7
    const int tig  = lane & 3;            // 0..3

    float acc[4][4][4];
#pragma unroll
    for (int mi = 0; mi < 4; mi++)
#pragma unroll
        for (int ni = 0; ni < 4; ni++)
#pragma unroll
            for (int r = 0; r < 4; r++) acc[mi][ni][r] = 0.0f;

    const float* Ag = A + (size_t)(bm + lrow) * lda + lcol;
    const float* Bg = B + (size_t)(bn + lrow) * ldb + lcol;
    const bool bvalid = (bn + lrow) < Nvalid;
    const float4 z4 = make_float4(0.f, 0.f, 0.f, 0.f);

    // preload k-tile 0
    float4 pa0 = *(const float4*)(Ag);
    float4 pa1 = *(const float4*)(Ag + 4);
    float4 pb0 = bvalid ? *(const float4*)(Bg) : z4;
    float4 pb1 = bvalid ? *(const float4*)(Bg + 4) : z4;

    int k0 = 0;
    for (;;) {
        // store current tile to smem (tf32-rounded)
        {
            uint4 va0 = make_uint4(f2tf32(pa0.x), f2tf32(pa0.y), f2tf32(pa0.z), f2tf32(pa0.w));
            uint4 va1 = make_uint4(f2tf32(pa1.x), f2tf32(pa1.y), f2tf32(pa1.z), f2tf32(pa1.w));
            uint4 vb0 = make_uint4(f2tf32(pb0.x), f2tf32(pb0.y), f2tf32(pb0.z), f2tf32(pb0.w));
            uint4 vb1 = make_uint4(f2tf32(pb1.x), f2tf32(pb1.y), f2tf32(pb1.z), f2tf32(pb1.w));
            *(uint4*)&As[lrow][lcol + 0] = va0;
            *(uint4*)&As[lrow][lcol + 4] = va1;
            *(uint4*)&Bs[lrow][lcol + 0] = vb0;
            *(uint4*)&Bs[lrow][lcol + 4] = vb1;
        }
        __syncthreads();

        const int knext = k0 + 16;
        const bool more = knext < K;
        if (more) {
            pa0 = *(const float4*)(Ag + knext);
            pa1 = *(const float4*)(Ag + knext + 4);
            pb0 = bvalid ? *(const float4*)(Bg + knext) : z4;
            pb1 = bvalid ? *(const float4*)(Bg + knext + 4) : z4;
        }

#pragma unroll
        for (int kk = 0; kk < 16; kk += 8) {
            uint32_t af[4][4], bf[4][2];
#pragma unroll
            for (int mi = 0; mi < 4; mi++) {
                const int r0 = wm + mi * 16 + gid;
                af[mi][0] = As[r0][kk + tig];
                af[mi][1] = As[r0 + 8][kk + tig];
                af[mi][2] = As[r0][kk + tig + 4];
                af[mi][3] = As[r0 + 8][kk + tig + 4];
            }
#pragma unroll
            for (int ni = 0; ni < 4; ni++) {
                const int n0 = wn + ni * 8 + gid;
                bf[ni][0] = Bs[n0][kk + tig];
                bf[ni][1] = Bs[n0][kk + tig + 4];
            }
#pragma unroll
            for (int mi = 0; mi < 4; mi++)
#pragma unroll
                for (int ni = 0; ni < 4; ni++)
                    mma_tf32(acc[mi][ni], af[mi], bf[ni]);
        }
        __syncthreads();
        if (!more) break;
        k0 = knext;
    }

    // epilogue
#pragma unroll
    for (int mi = 0; mi < 4; mi++) {
        const int row0 = bm + wm + mi * 16 + gid;
#pragma unroll
        for (int ni = 0; ni < 4; ni++) {
            const int col0 = bn + wn + ni * 8 + tig * 2;
            if (col0 >= Nvalid) continue;
            float v0 = acc[mi][ni][0], v1 = acc[mi][ni][1];
            float v2 = acc[mi][ni][2], v3 = acc[mi][ni][3];
            if (ACT == 1) {
                float b0 = bias[col0], b1 = bias[col0 + 1];
                v0 += b0; v1 += b1; v2 += b0; v3 += b1;
                v0 = (v0 > 20.0f) ? v0 : log1pf(__expf(v0));
                v1 = (v1 > 20.0f) ? v1 : log1pf(__expf(v1));
                v2 = (v2 > 20.0f) ? v2 : log1pf(__expf(v2));
                v3 = (v3 > 20.0f) ? v3 : log1pf(__expf(v3));
            }
            C[(size_t)row0 * ldc + col0]           = v0;
            C[(size_t)row0 * ldc + col0 + 1]       = v1;
            C[(size_t)(row0 + 8) * ldc + col0]     = v2;
            C[(size_t)(row0 + 8) * ldc + col0 + 1] = v3;
        }
    }
}

// ---------------- causal depthwise conv (k=4) + SiLU ----------------
__global__ void conv_silu_kernel(
    const float* __restrict__ xz,       // [ML, 2*DINNER], x_ssm = cols [0,1024)
    const float* __restrict__ w,        // [DINNER, 1, 4]
    const float* __restrict__ cb,       // [DINNER]
    float* __restrict__ out)            // [ML, DINNER]
{
    int idx = blockIdx.x * blockDim.x + threadIdx.x;
    if (idx >= ML * DINNER) return;
    int d  = idx & (DINNER - 1);
    int bl = idx >> 10;
    int l  = bl & (SEQ - 1);

    float w0 = w[d * 4 + 0], w1 = w[d * 4 + 1], w2 = w[d * 4 + 2], w3 = w[d * 4 + 3];
    const float* base = xz + (size_t)bl * (2 * DINNER) + d;
    float acc = cb[d] + base[0] * w3;
    if (l >= 1) acc += base[-(2 * DINNER)]     * w2;
    if (l >= 2) acc += base[-2 * (2 * DINNER)] * w1;
    if (l >= 3) acc += base[-3 * (2 * DINNER)] * w0;
    out[idx] = acc * sigmoid_f(acc);
}

// ---------------- selective scan: 16 lanes per (b,d) channel ----------------
__global__ void scan_kernel(
    const float* __restrict__ dt,     // [ML, DINNER]
    const float* __restrict__ xc,     // [ML, DINNER]
    const float* __restrict__ xdbl,   // [ML, 96]  (B at 64, C at 80)
    const float* __restrict__ A_log,  // [DINNER, DSTATE]
    float* __restrict__ y)            // [ML, DINNER]
{
    int gtid = blockIdx.x * blockDim.x + threadIdx.x;
    int ch = gtid >> 4;                  // channel 0..2047
    int n  = gtid & 15;                  // state index
    if (ch >= BATCH * DINNER) return;
    int b = ch / DINNER;
    int d = ch - b * DINNER;

    const float Aval = -__expf(A_log[d * DSTATE + n]);
    float h = 0.0f;

    const float* bp = xdbl + (size_t)b * SEQ * XDBLW + DTRANK + n;
    const float* cp = bp + DSTATE;
    size_t base = (size_t)b * SEQ * DINNER + d;

    for (int l = 0; l < SEQ; l++) {
        float dtv = dt[base];
        float xv  = xc[base];
        float Bv  = bp[0];
        float Cv  = cp[0];
        h = __expf(dtv * Aval) * h + (dtv * xv) * Bv;
        float yv = h * Cv;
        yv += __shfl_down_sync(0xffffffffu, yv, 8, 16);
        yv += __shfl_down_sync(0xffffffffu, yv, 4, 16);
        yv += __shfl_down_sync(0xffffffffu, yv, 2, 16);
        yv += __shfl_down_sync(0xffffffffu, yv, 1, 16);
        if (n == 0) y[base] = yv;
        base += DINNER;
        bp += XDBLW;
        cp += XDBLW;
    }
}

// ---------------- y = (y_scan + x_conv*D) * silu(z) ----------------
__global__ void gate_kernel(
    const float* __restrict__ ys,
    const float* __restrict__ xc,
    const float* __restrict__ xz,      // z = cols [1024,2048)
    const float* __restrict__ Dp,
    float* __restrict__ out)
{
    int idx = blockIdx.x * blockDim.x + threadIdx.x;
    if (idx >= ML * DINNER) return;
    int d  = idx & (DINNER - 1);
    int bl = idx >> 10;
    float z = xz[(size_t)bl * (2 * DINNER) + DINNER + d];
    out[idx] = (ys[idx] + xc[idx] * Dp[d]) * (z * sigmoid_f(z));
}

// ---------------- launch ----------------
extern "C" void kernel_launch(void* const* d_in, const int* in_sizes, int n_in,
                              void* d_out, int out_size)
{
    const float* x      = (const float*)d_in[0];
    const float* W_in   = (const float*)d_in[1];
    const float* conv_w = (const float*)d_in[2];
    const float* conv_b = (const float*)d_in[3];
    const float* W_x    = (const float*)d_in[4];
    const float* W_dt   = (const float*)d_in[5];
    const float* b_dt   = (const float*)d_in[6];
    const float* A_log  = (const float*)d_in[7];
    const float* Dp     = (const float*)d_in[8];
    const float* W_out  = (const float*)d_in[9];
    float* out = (float*)d_out;

    float *xz, *xconv, *xdbl, *dt, *yscan, *ygate;
    cudaGetSymbolAddress((void**)&xz,    g_xz);
    cudaGetSymbolAddress((void**)&xconv, g_xconv);
    cudaGetSymbolAddress((void**)&xdbl,  g_xdbl);
    cudaGetSymbolAddress((void**)&dt,    g_dt);
    cudaGetSymbolAddress((void**)&yscan, g_yscan);
    cudaGetSymbolAddress((void**)&ygate, g_ygate);

    // 1) xz = x @ W_in^T   [4096, 2048]
    gemm_tf32<0><<<dim3(2 * DINNER / 128, ML / 128), 256>>>(
        x, DMODEL, W_in, DMODEL, xz, 2 * DINNER, DMODEL, 2 * DINNER, nullptr);

    // 2) causal conv + SiLU  [4096, 1024]
    conv_silu_kernel<<<(ML * DINNER) / 256, 256>>>(xz, conv_w, conv_b, xconv);

    // 3) x_dbl = x_conv @ W_x^T  [4096, 96]  (N padded to 128, guarded)
    gemm_tf32<0><<<dim3(1, ML / 128), 256>>>(
        xconv, DINNER, W_x, DINNER, xdbl, XDBLW, DINNER, XDBLW, nullptr);

    // 4) dt = softplus(dt_raw @ W_dt^T + b_dt)  [4096, 1024]
    gemm_tf32<1><<<dim3(DINNER / 128, ML / 128), 256>>>(
        xdbl, XDBLW, W_dt, DTRANK, dt, DINNER, DTRANK, DINNER, b_dt);

    // 5) selective scan  [4096, 1024]
    scan_kernel<<<(BATCH * DINNER * DSTATE) / 256, 256>>>(dt, xconv, xdbl, A_log, yscan);

    // 6) gating
    gate_kernel<<<(ML * DINNER) / 256, 256>>>(yscan, xconv, xz, Dp, ygate);

    // 7) out = y @ W_out^T  [4096, 1024]
    gemm_tf32<0><<<dim3(DMODEL / 128, ML / 128), 256>>>(
        ygate, DINNER, W_out, DINNER, out, DMODEL, DINNER, DMODEL, nullptr);
}